// round 10
// baseline (speedup 1.0000x reference)
#include <cuda_runtime.h>
#include <cuda_fp16.h>
#include <math.h>
#include <stdint.h>

#define DIMC 384
#define NH 6
#define HD 64
#define MLPD 1536
#define BATCH 8
#define SEQ 1024
#define M_TOT (BATCH*SEQ)
#define LN_EPS 1e-5f

#define NW_QKV (3*DIMC*DIMC)
#define NW_PROJ (DIMC*DIMC)
#define NW_1 (MLPD*DIMC)
#define NW_2 (DIMC*MLPD)

__device__ __half g_h[M_TOT * DIMC];
__device__ __half g_qkv[M_TOT * 3 * DIMC];
__device__ __half g_vt[BATCH * NH * HD * SEQ];
__device__ __half g_ao[M_TOT * DIMC];
__device__ float  g_x1[M_TOT * DIMC];
__device__ __half g_m[M_TOT * MLPD];
__device__ __half g_wq[NW_QKV];
__device__ __half g_wp[NW_PROJ];
__device__ __half g_w1[NW_1];
__device__ __half g_w2[NW_2];

// fp16 pair permutation within 16-element k-groups: pair p -> slot (p%4)*2 + p/4,
// so an 8-byte load at half-offset 4j yields pairs (j, j+4) = one m16n8k16
// fragment register pair.
__device__ __forceinline__ int perm16h(int c) {
    int p = (c >> 1) & 7;
    int s = ((p & 3) << 1) | (p >> 2);
    return (c & ~15) | (s << 1) | (c & 1);
}
__device__ __forceinline__ int pairdst(int c0) {
    int p = (c0 >> 1) & 7;
    int s = ((p & 3) << 1) | (p >> 2);
    return (c0 & ~15) | (s << 1);
}

__device__ __forceinline__ void mma_f16(float c[4], uint32_t a0, uint32_t a1,
                                        uint32_t a2, uint32_t a3,
                                        uint32_t b0, uint32_t b1) {
    asm volatile(
        "mma.sync.aligned.m16n8k16.row.col.f32.f16.f16.f32 "
        "{%0,%1,%2,%3},{%4,%5,%6,%7},{%8,%9},{%0,%1,%2,%3};\n"
        : "+f"(c[0]), "+f"(c[1]), "+f"(c[2]), "+f"(c[3])
        : "r"(a0), "r"(a1), "r"(a2), "r"(a3), "r"(b0), "r"(b1));
}

__device__ __forceinline__ void cpa16(uint32_t s, const void* g) {
    asm volatile("cp.async.cg.shared.global [%0], [%1], 16;" :: "r"(s), "l"(g));
}

// ============================================================
// one-shot weight rounding to fp16 + pair permutation along K
// ============================================================
__global__ __launch_bounds__(256)
void round_w(const float* __restrict__ a, __half* __restrict__ oa,
             const float* __restrict__ b, __half* __restrict__ ob,
             const float* __restrict__ c, __half* __restrict__ oc,
             const float* __restrict__ d, __half* __restrict__ od) {
    int i = blockIdx.x * 256 + threadIdx.x;
    int p = perm16h(i);
    if (i < NW_QKV)  oa[p] = __float2half_rn(a[i]);
    if (i < NW_PROJ) ob[p] = __float2half_rn(b[i]);
    if (i < NW_1) { oc[p] = __float2half_rn(c[i]); od[p] = __float2half_rn(d[i]); }
}

// ============================================================
// LayerNorm: one warp per row; fp16 pair-permuted output
// ============================================================
__global__ __launch_bounds__(256)
void ln_kernel(const float* __restrict__ x, const float* __restrict__ w,
               const float* __restrict__ b, __half* __restrict__ out) {
    int lane = threadIdx.x & 31;
    int row = blockIdx.x * 8 + (threadIdx.x >> 5);
    const float* xr = x + (size_t)row * DIMC;

    float v[12];
    float s = 0.f;
    #pragma unroll
    for (int i = 0; i < 12; i++) { v[i] = xr[lane + 32 * i]; s += v[i]; }
    #pragma unroll
    for (int o = 16; o > 0; o >>= 1) s += __shfl_xor_sync(0xffffffff, s, o);
    float mean = s * (1.0f / DIMC);

    float q = 0.f;
    #pragma unroll
    for (int i = 0; i < 12; i++) { float d = v[i] - mean; q += d * d; }
    #pragma unroll
    for (int o = 16; o > 0; o >>= 1) q += __shfl_xor_sync(0xffffffff, q, o);
    float r = rsqrtf(q * (1.0f / DIMC) + LN_EPS);

    __half* orow = out + (size_t)row * DIMC;
    #pragma unroll
    for (int i = 0; i < 12; i++) {
        int c = lane + 32 * i;
        orow[perm16h(c)] = __float2half_rn((v[i] - mean) * r * w[c] + b[c]);
    }
}

// ============================================================
// FP16 TC GEMM: C[M,N] = A[M,K] @ W[N,K]^T (+epilogue)
// BK=64, 2-stage double buffer, prefetch-inside-loop:
// ONE wait_group + ONE __syncthreads per 64-k (64 HMMA/warp between
// barriers at MT=128). smem stride 72 halfs.
// EPI 0: qkv out (Q/K perm16h; V transposed+permuted to vt)
// EPI 1: +bias +res, fp32 out   EPI 2: +bias, GELU, fp16 perm out
// ============================================================
#define SH 72
#define GEMM_SMEM(MT) (2 * ((MT) + 128) * SH * 2)

template <int EPI, int MT>
__global__ __launch_bounds__(256, 2)
void gemm_tc(const __half* __restrict__ A, const __half* __restrict__ W,
             const float* __restrict__ bias, const float* __restrict__ res,
             float* __restrict__ Cf, __half* __restrict__ Ch,
             __half* __restrict__ vt, int M, int N, int K) {
    extern __shared__ __half smemh[];
    const int ASLOT = MT * SH;
    const int BSLOT = 128 * SH;
    __half* As = smemh;                  // [2][ASLOT]
    __half* Bs = smemh + 2 * ASLOT;      // [2][BSLOT]
    uint32_t As_u = (uint32_t)__cvta_generic_to_shared(As);
    uint32_t Bs_u = (uint32_t)__cvta_generic_to_shared(Bs);

    int tid = threadIdx.x;
    int lane = tid & 31, wid = tid >> 5;
    int wm = wid >> 2, wn = wid & 3;
    int j = lane & 3, lr4 = lane >> 2;
    int m0 = blockIdx.y * MT, n0 = blockIdx.x * 128;

    const int ACH = MT * 8 / 256;        // A 16B-chunks per thread (4 or 2)
    const int MI = MT / 32;
    float acc[MI][4][4];
    #pragma unroll
    for (int mi = 0; mi < MI; mi++)
        #pragma unroll
        for (int ni = 0; ni < 4; ni++)
            #pragma unroll
            for (int r = 0; r < 4; r++) acc[mi][ni][r] = 0.f;

    int T = K / 64;

    // prologue: stage 0
    {
        #pragma unroll
        for (int cch = 0; cch < ACH; cch++) {
            int ch = tid + cch * 256;
            int row_ = ch >> 3, off = (ch & 7) * 8;
            cpa16(As_u + (row_ * SH + off) * 2,
                  A + (size_t)(m0 + row_) * K + off);
        }
        #pragma unroll
        for (int cch = 0; cch < 4; cch++) {
            int ch = tid + cch * 256;
            int row_ = ch >> 3, off = (ch & 7) * 8;
            cpa16(Bs_u + (row_ * SH + off) * 2,
                  W + (size_t)(n0 + row_) * K + off);
        }
        asm volatile("cp.async.commit_group;");
    }

    for (int t = 0; t < T; t++) {
        asm volatile("cp.async.wait_group 0;");
        __syncthreads();
        if (t + 1 < T) {
            int sl = (t + 1) & 1;
            #pragma unroll
            for (int cch = 0; cch < ACH; cch++) {
                int ch = tid + cch * 256;
                int row_ = ch >> 3, off = (ch & 7) * 8;
                cpa16(As_u + (sl * ASLOT + row_ * SH + off) * 2,
                      A + (size_t)(m0 + row_) * K + (t + 1) * 64 + off);
            }
            #pragma unroll
            for (int cch = 0; cch < 4; cch++) {
                int ch = tid + cch * 256;
                int row_ = ch >> 3, off = (ch & 7) * 8;
                cpa16(Bs_u + (sl * BSLOT + row_ * SH + off) * 2,
                      W + (size_t)(n0 + row_) * K + (t + 1) * 64 + off);
            }
            asm volatile("cp.async.commit_group;");
        }
        const __half* Ast = As + (t & 1) * ASLOT;
        const __half* Bst = Bs + (t & 1) * BSLOT;
        #pragma unroll
        for (int kk = 0; kk < 64; kk += 16) {
            uint2 afA[MI], afB[MI];
            #pragma unroll
            for (int mi = 0; mi < MI; mi++) {
                int mr = wm * (MT / 2) + mi * 16 + lr4;
                afA[mi] = *(const uint2*)&Ast[mr * SH + kk + 4 * j];
                afB[mi] = *(const uint2*)&Ast[(mr + 8) * SH + kk + 4 * j];
            }
            #pragma unroll
            for (int ni = 0; ni < 4; ni++) {
                int nr = wn * 32 + ni * 8 + lr4;
                uint2 bf = *(const uint2*)&Bst[nr * SH + kk + 4 * j];
                #pragma unroll
                for (int mi = 0; mi < MI; mi++)
                    mma_f16(acc[mi][ni], afA[mi].x, afB[mi].x,
                            afA[mi].y, afB[mi].y, bf.x, bf.y);
            }
        }
    }

    #pragma unroll
    for (int mi = 0; mi < MI; mi++) {
        int r = m0 + wm * (MT / 2) + mi * 16 + lr4;
        #pragma unroll
        for (int ni = 0; ni < 4; ni++) {
            int c = n0 + wn * 32 + ni * 8 + 2 * j;
            float v[4] = {acc[mi][ni][0], acc[mi][ni][1], acc[mi][ni][2], acc[mi][ni][3]};
            int rr[2] = {r, r + 8};
            #pragma unroll
            for (int half_ = 0; half_ < 2; half_++) {
                float x0 = v[half_ * 2 + 0], x1 = v[half_ * 2 + 1];
                if (EPI == 0) {
                    if (c < 768) {
                        int dst = pairdst(c);
                        *(__half2*)(Ch + (size_t)rr[half_] * N + dst) =
                            __floats2half2_rn(x0, x1);
                    } else {
                        int b_ = rr[half_] >> 10;
                        int n_ = rr[half_] & (SEQ - 1);
                        int np = perm16h(n_);
                        int d0 = c - 768;
                        __half* vtb = vt + ((size_t)b_ * NH * HD + d0) * SEQ;
                        vtb[np]       = __float2half_rn(x0);
                        vtb[SEQ + np] = __float2half_rn(x1);
                    }
                }
                if (EPI == 1) {
                    const float* rrow = res + (size_t)rr[half_] * N;
                    x0 += bias[c] + rrow[c];
                    x1 += bias[c + 1] + rrow[c + 1];
                    *(float2*)(Cf + (size_t)rr[half_] * N + c) = make_float2(x0, x1);
                }
                if (EPI == 2) {
                    x0 += bias[c];
                    x1 += bias[c + 1];
                    x0 = 0.5f * x0 * (1.0f + erff(x0 * 0.70710678118654752f));
                    x1 = 0.5f * x1 * (1.0f + erff(x1 * 0.70710678118654752f));
                    int dst = pairdst(c);
                    *(__half2*)(Ch + (size_t)rr[half_] * N + dst) =
                        __floats2half2_rn(x0, x1);
                }
            }
        }
    }
}

// ============================================================
// L2Q attention, fp16 mma (unchanged from R9): 256 thr / 8 warps,
// Q tile 128, K tile 64, double-buffered cp.async, warp-private F.
// ============================================================
#define AKH 80
#define KV_TILE (64*AKH)
#define FPAD (16*AKH)
#define ATTN_SMEM ((4*KV_TILE + 8*FPAD) * 2)   // 61440 B

__global__ __launch_bounds__(256, 3)
void attn_tc(const __half* __restrict__ qkv, const __half* __restrict__ vt,
             const float* __restrict__ alpha, const float* __restrict__ beta,
             const float* __restrict__ gamma, __half* __restrict__ ao) {
    extern __shared__ __half smh[];
    __half* Ks = smh;
    __half* Vs = smh + 2 * KV_TILE;
    __half* Fw = smh + 4 * KV_TILE;
    uint32_t Ks_u = (uint32_t)__cvta_generic_to_shared(Ks);
    uint32_t Vs_u = (uint32_t)__cvta_generic_to_shared(Vs);

    int tid = threadIdx.x, lane = tid & 31, wid = tid >> 5;
    int j = lane & 3, lr4 = lane >> 2;
    int bh = blockIdx.y;
    int b = bh / NH, h = bh % NH;
    int r0 = blockIdx.x * 128;
    float al = alpha[h], be = beta[h], ga = gamma[h];

    const __half* qbase = qkv + (size_t)b * SEQ * (3 * DIMC) + h * HD;
    const __half* kbase = qbase + DIMC;
    const __half* vtb = vt + (size_t)bh * HD * SEQ;

    int row0 = wid * 16 + lr4;
    __half* fw = Fw + wid * FPAD;

    uint32_t qf[4][4];
    {
        const __half* qlo = qbase + (size_t)(r0 + row0) * (3 * DIMC);
        const __half* qhi = qlo + 8 * (3 * DIMC);
        #pragma unroll
        for (int dk = 0; dk < 4; dk++) {
            uint2 q0 = *(const uint2*)(qlo + dk * 16 + 4 * j);
            uint2 q1 = *(const uint2*)(qhi + dk * 16 + 4 * j);
            qf[dk][0] = q0.x; qf[dk][1] = q1.x;
            qf[dk][2] = q0.y; qf[dk][3] = q1.y;
        }
    }

    float oacc[8][4];
    #pragma unroll
    for (int i = 0; i < 8; i++)
        #pragma unroll
        for (int r = 0; r < 4; r++) oacc[i][r] = 0.f;
    float den0 = 0.f, den1 = 0.f;

    int lrow = tid >> 2;
    int lq = (tid & 3) * 16;
    uint32_t s_off = (lrow * AKH + lq) * 2;

    {
        const __half* kr = kbase + (size_t)lrow * (3 * DIMC) + lq;
        const __half* vr = vtb + (size_t)lrow * SEQ + lq;
        cpa16(Ks_u + s_off,      kr);
        cpa16(Ks_u + s_off + 16, kr + 8);
        cpa16(Vs_u + s_off,      vr);
        cpa16(Vs_u + s_off + 16, vr + 8);
        asm volatile("cp.async.commit_group;");
    }

    const int NT = SEQ / 64;
    for (int t = 0; t < NT; t++) {
        int s = t & 1;
        asm volatile("cp.async.wait_group 0;");
        __syncthreads();
        if (t + 1 < NT) {
            int s2 = s ^ 1;
            const __half* kr = kbase + (size_t)((t + 1) * 64 + lrow) * (3 * DIMC) + lq;
            const __half* vr = vtb + (size_t)lrow * SEQ + (t + 1) * 64 + lq;
            uint32_t kb = Ks_u + s2 * KV_TILE * 2 + s_off;
            uint32_t vb = Vs_u + s2 * KV_TILE * 2 + s_off;
            cpa16(kb, kr);      cpa16(kb + 16, kr + 8);
            cpa16(vb, vr);      cpa16(vb + 16, vr + 8);
            asm volatile("cp.async.commit_group;");
        }
        const __half* Kt = Ks + s * KV_TILE;
        const __half* Vt = Vs + s * KV_TILE;

        #pragma unroll
        for (int ni = 0; ni < 8; ni++) {
            float sa[4] = {0.f, 0.f, 0.f, 0.f};
            int br = ni * 8 + lr4;
            #pragma unroll
            for (int dk = 0; dk < 4; dk++) {
                uint2 bf = *(const uint2*)&Kt[br * AKH + dk * 16 + 4 * j];
                mma_f16(sa, qf[dk][0], qf[dk][1], qf[dk][2], qf[dk][3], bf.x, bf.y);
            }
            float s0 = sa[0] * 0.125f, s1 = sa[1] * 0.125f;
            float s2 = sa[2] * 0.125f, s3 = sa[3] * 0.125f;
            float f0 = fmaxf(fmaf(al * s0, s0, fmaf(be, s0, ga)), 0.f);
            float f1 = fmaxf(fmaf(al * s1, s1, fmaf(be, s1, ga)), 0.f);
            float f2 = fmaxf(fmaf(al * s2, s2, fmaf(be, s2, ga)), 0.f);
            float f3 = fmaxf(fmaf(al * s3, s3, fmaf(be, s3, ga)), 0.f);
            den0 += f0 + f1;
            den1 += f2 + f3;
            int dst = pairdst(ni * 8 + 2 * j);
            *(__half2*)&fw[lr4 * AKH + dst]       = __floats2half2_rn(f0, f1);
            *(__half2*)&fw[(lr4 + 8) * AKH + dst] = __floats2half2_rn(f2, f3);
        }
        __syncwarp();

        #pragma unroll
        for (int kk = 0; kk < 64; kk += 16) {
            uint2 fa0 = *(const uint2*)&fw[lr4 * AKH + kk + 4 * j];
            uint2 fa1 = *(const uint2*)&fw[(lr4 + 8) * AKH + kk + 4 * j];
            #pragma unroll
            for (int ni = 0; ni < 8; ni++) {
                int nd = ni * 8 + lr4;
                uint2 bf = *(const uint2*)&Vt[nd * AKH + kk + 4 * j];
                mma_f16(oacc[ni], fa0.x, fa1.x, fa0.y, fa1.y, bf.x, bf.y);
            }
        }
        __syncwarp();
    }

    den0 += __shfl_xor_sync(0xffffffff, den0, 1);
    den0 += __shfl_xor_sync(0xffffffff, den0, 2);
    den1 += __shfl_xor_sync(0xffffffff, den1, 1);
    den1 += __shfl_xor_sync(0xffffffff, den1, 2);
    float di0 = 1.0f / (den0 + 1e-6f);
    float di1 = 1.0f / (den1 + 1e-6f);

    __half* olo = ao + (size_t)(b * SEQ + r0 + row0) * DIMC + h * HD;
    __half* ohi = olo + 8 * DIMC;
    #pragma unroll
    for (int ni = 0; ni < 8; ni++) {
        int dst = pairdst(ni * 8 + 2 * j);
        *(__half2*)(olo + dst) = __floats2half2_rn(oacc[ni][0] * di0, oacc[ni][1] * di0);
        *(__half2*)(ohi + dst) = __floats2half2_rn(oacc[ni][2] * di1, oacc[ni][3] * di1);
    }
}

// ============================================================
// launch
// ============================================================
extern "C" void kernel_launch(void* const* d_in, const int* in_sizes, int n_in,
                              void* d_out, int out_size) {
    const float* x      = (const float*)d_in[0];
    const float* qkv_w  = (const float*)d_in[1];
    const float* proj_w = (const float*)d_in[2];
    const float* proj_b = (const float*)d_in[3];
    const float* alpha  = (const float*)d_in[4];
    const float* beta   = (const float*)d_in[5];
    const float* gamma  = (const float*)d_in[6];
    const float* ln1_w  = (const float*)d_in[7];
    const float* ln1_b  = (const float*)d_in[8];
    const float* ln2_w  = (const float*)d_in[9];
    const float* ln2_b  = (const float*)d_in[10];
    const float* w1     = (const float*)d_in[11];
    const float* b1     = (const float*)d_in[12];
    const float* w2     = (const float*)d_in[13];
    const float* b2     = (const float*)d_in[14];
    float* out = (float*)d_out;

    __half *h, *qkv, *vt, *ao, *m, *wq, *wp, *ww1, *ww2;
    float *x1;
    cudaGetSymbolAddress((void**)&h,   g_h);
    cudaGetSymbolAddress((void**)&qkv, g_qkv);
    cudaGetSymbolAddress((void**)&vt,  g_vt);
    cudaGetSymbolAddress((void**)&ao,  g_ao);
    cudaGetSymbolAddress((void**)&x1,  g_x1);
    cudaGetSymbolAddress((void**)&m,   g_m);
    cudaGetSymbolAddress((void**)&wq,  g_wq);
    cudaGetSymbolAddress((void**)&wp,  g_wp);
    cudaGetSymbolAddress((void**)&ww1, g_w1);
    cudaGetSymbolAddress((void**)&ww2, g_w2);

    cudaFuncSetAttribute((const void*)gemm_tc<0,128>, cudaFuncAttributeMaxDynamicSharedMemorySize, GEMM_SMEM(128));
    cudaFuncSetAttribute((const void*)gemm_tc<2,128>, cudaFuncAttributeMaxDynamicSharedMemorySize, GEMM_SMEM(128));
    cudaFuncSetAttribute((const void*)gemm_tc<1,64>,  cudaFuncAttributeMaxDynamicSharedMemorySize, GEMM_SMEM(64));
    cudaFuncSetAttribute((const void*)attn_tc,        cudaFuncAttributeMaxDynamicSharedMemorySize, ATTN_SMEM);

    round_w<<<(NW_1 + 255) / 256, 256>>>(qkv_w, wq, proj_w, wp, w1, ww1, w2, ww2);
    ln_kernel<<<M_TOT / 8, 256>>>(x, ln1_w, ln1_b, h);
    gemm_tc<0,128><<<dim3(3 * DIMC / 128, M_TOT / 128), 256, GEMM_SMEM(128)>>>(
        h, wq, nullptr, nullptr, nullptr, qkv, vt, M_TOT, 3 * DIMC, DIMC);
    attn_tc<<<dim3(SEQ / 128, BATCH * NH), 256, ATTN_SMEM>>>(qkv, vt, alpha, beta, gamma, ao);
    gemm_tc<1,64><<<dim3(DIMC / 128, M_TOT / 64), 256, GEMM_SMEM(64)>>>(
        ao, wp, proj_b, x, x1, nullptr, nullptr, M_TOT, DIMC, DIMC);
    ln_kernel<<<M_TOT / 8, 256>>>(x1, ln2_w, ln2_b, h);
    gemm_tc<2,128><<<dim3(MLPD / 128, M_TOT / 128), 256, GEMM_SMEM(128)>>>(
        h, ww1, b1, nullptr, nullptr, m, nullptr, M_TOT, MLPD, DIMC);
    gemm_tc<1,64><<<dim3(DIMC / 128, M_TOT / 64), 256, GEMM_SMEM(64)>>>(
        m, ww2, b2, x1, out, nullptr, nullptr, M_TOT, DIMC, MLPD);
}

// round 11
// speedup vs baseline: 1.0608x; 1.0608x over previous
#include <cuda_runtime.h>
#include <cuda_fp16.h>
#include <math.h>
#include <stdint.h>

#define DIMC 384
#define NH 6
#define HD 64
#define MLPD 1536
#define BATCH 8
#define SEQ 1024
#define M_TOT (BATCH*SEQ)
#define LN_EPS 1e-5f

#define NW_QKV (3*DIMC*DIMC)
#define NW_PROJ (DIMC*DIMC)
#define NW_1 (MLPD*DIMC)
#define NW_2 (DIMC*MLPD)

__device__ __half g_h[M_TOT * DIMC];
__device__ __half g_qkv[M_TOT * 3 * DIMC];
__device__ __half g_vt[BATCH * NH * HD * SEQ];
__device__ __half g_ao[M_TOT * DIMC];
__device__ float  g_x1[M_TOT * DIMC];
__device__ __half g_m[M_TOT * MLPD];
__device__ __half g_wq[NW_QKV];
__device__ __half g_wp[NW_PROJ];
__device__ __half g_w1[NW_1];
__device__ __half g_w2[NW_2];

// fp16 pair permutation within 16-element k-groups: pair p -> slot (p%4)*2 + p/4,
// so an 8-byte load at half-offset 4j yields pairs (j, j+4) = one m16n8k16
// fragment register pair.
__device__ __forceinline__ int perm16h(int c) {
    int p = (c >> 1) & 7;
    int s = ((p & 3) << 1) | (p >> 2);
    return (c & ~15) | (s << 1) | (c & 1);
}
__device__ __forceinline__ int pairdst(int c0) {
    int p = (c0 >> 1) & 7;
    int s = ((p & 3) << 1) | (p >> 2);
    return (c0 & ~15) | (s << 1);
}

__device__ __forceinline__ void mma_f16(float c[4], uint32_t a0, uint32_t a1,
                                        uint32_t a2, uint32_t a3,
                                        uint32_t b0, uint32_t b1) {
    asm volatile(
        "mma.sync.aligned.m16n8k16.row.col.f32.f16.f16.f32 "
        "{%0,%1,%2,%3},{%4,%5,%6,%7},{%8,%9},{%0,%1,%2,%3};\n"
        : "+f"(c[0]), "+f"(c[1]), "+f"(c[2]), "+f"(c[3])
        : "r"(a0), "r"(a1), "r"(a2), "r"(a3), "r"(b0), "r"(b1));
}

__device__ __forceinline__ void cpa16(uint32_t s, const void* g) {
    asm volatile("cp.async.cg.shared.global [%0], [%1], 16;" :: "r"(s), "l"(g));
}

// ============================================================
// one-shot weight rounding to fp16 + pair permutation along K
// vectorized: 8 elements (one perm group half) per thread
// ============================================================
__global__ __launch_bounds__(256)
void round_w(const float* __restrict__ a, __half* __restrict__ oa,
             const float* __restrict__ b, __half* __restrict__ ob,
             const float* __restrict__ c, __half* __restrict__ oc,
             const float* __restrict__ d, __half* __restrict__ od) {
    int i0 = (blockIdx.x * 256 + threadIdx.x) * 8;
    #pragma unroll
    for (int g = 0; g < 2; g++) {
        int i = i0 + g * 4;
        float4 va, vb, vc, vd;
        bool da = i < NW_QKV, db = i < NW_PROJ, dc = i < NW_1;
        if (da) va = *(const float4*)(a + i);
        if (db) vb = *(const float4*)(b + i);
        if (dc) { vc = *(const float4*)(c + i); vd = *(const float4*)(d + i); }
        const float* pa = &va.x; const float* pb = &vb.x;
        const float* pc = &vc.x; const float* pd = &vd.x;
        #pragma unroll
        for (int u = 0; u < 4; u++) {
            int p = perm16h(i + u);
            if (da) oa[p] = __float2half_rn(pa[u]);
            if (db) ob[p] = __float2half_rn(pb[u]);
            if (dc) { oc[p] = __float2half_rn(pc[u]); od[p] = __float2half_rn(pd[u]); }
        }
    }
}

// ============================================================
// LayerNorm: one warp per row; fp16 pair-permuted output
// ============================================================
__global__ __launch_bounds__(256)
void ln_kernel(const float* __restrict__ x, const float* __restrict__ w,
               const float* __restrict__ b, __half* __restrict__ out) {
    int lane = threadIdx.x & 31;
    int row = blockIdx.x * 8 + (threadIdx.x >> 5);
    const float* xr = x + (size_t)row * DIMC;

    float v[12];
    float s = 0.f;
    #pragma unroll
    for (int i = 0; i < 12; i++) { v[i] = xr[lane + 32 * i]; s += v[i]; }
    #pragma unroll
    for (int o = 16; o > 0; o >>= 1) s += __shfl_xor_sync(0xffffffff, s, o);
    float mean = s * (1.0f / DIMC);

    float q = 0.f;
    #pragma unroll
    for (int i = 0; i < 12; i++) { float d = v[i] - mean; q += d * d; }
    #pragma unroll
    for (int o = 16; o > 0; o >>= 1) q += __shfl_xor_sync(0xffffffff, q, o);
    float r = rsqrtf(q * (1.0f / DIMC) + LN_EPS);

    __half* orow = out + (size_t)row * DIMC;
    #pragma unroll
    for (int i = 0; i < 12; i++) {
        int c = lane + 32 * i;
        orow[perm16h(c)] = __float2half_rn((v[i] - mean) * r * w[c] + b[c]);
    }
}

// ============================================================
// FP16 TC GEMM: C[M,N] = A[M,K] @ W[N,K]^T (+epilogue)
// BK=32, 4-stage cp.async (wait_group 2), 256 thr, warps 2x4.
// Both kk-halves' fragments loaded into distinct regs BEFORE the
// 32 MMAs -> half1's LDS latency hidden under half0's MMAs.
// EPI 0: qkv out (Q/K perm16h; V transposed+permuted to vt)
// EPI 1: +bias +res, fp32 out   EPI 2: +bias, GELU, fp16 perm out
// ============================================================
#define SH 48
#define GEMM_SMEM(MT) (4 * ((MT) + 128) * SH * 2)

template <int EPI, int MT>
__global__ __launch_bounds__(256, 2)
void gemm_tc(const __half* __restrict__ A, const __half* __restrict__ W,
             const float* __restrict__ bias, const float* __restrict__ res,
             float* __restrict__ Cf, __half* __restrict__ Ch,
             __half* __restrict__ vt, int M, int N, int K) {
    extern __shared__ __half smemh[];
    const int ASLOT = MT * SH;
    const int BSLOT = 128 * SH;
    __half* As = smemh;                  // [4][ASLOT]
    __half* Bs = smemh + 4 * ASLOT;      // [4][BSLOT]
    uint32_t As_u = (uint32_t)__cvta_generic_to_shared(As);
    uint32_t Bs_u = (uint32_t)__cvta_generic_to_shared(Bs);

    int tid = threadIdx.x;
    int lane = tid & 31, wid = tid >> 5;
    int wm = wid >> 2, wn = wid & 3;
    int j = lane & 3, lr4 = lane >> 2;
    int m0 = blockIdx.y * MT, n0 = blockIdx.x * 128;

    const int ACH = MT / 64;             // A 16B-chunks per thread (2 or 1)
    const int MI = MT / 32;
    float acc[MI][4][4];
    #pragma unroll
    for (int mi = 0; mi < MI; mi++)
        #pragma unroll
        for (int ni = 0; ni < 4; ni++)
            #pragma unroll
            for (int r = 0; r < 4; r++) acc[mi][ni][r] = 0.f;

    int T = K / 32;

    // prologue: stages 0..2
    #pragma unroll
    for (int t = 0; t < 3; t++) {
        #pragma unroll
        for (int cch = 0; cch < ACH; cch++) {
            int ch = tid + cch * 256;
            int row_ = ch >> 2, off = (ch & 3) * 8;
            cpa16(As_u + (t * ASLOT + row_ * SH + off) * 2,
                  A + (size_t)(m0 + row_) * K + t * 32 + off);
        }
        #pragma unroll
        for (int cch = 0; cch < 2; cch++) {
            int ch = tid + cch * 256;
            int row_ = ch >> 2, off = (ch & 3) * 8;
            cpa16(Bs_u + (t * BSLOT + row_ * SH + off) * 2,
                  W + (size_t)(n0 + row_) * K + t * 32 + off);
        }
        asm volatile("cp.async.commit_group;");
    }

    for (int t = 0; t < T; t++) {
        if (t + 3 <= T) asm volatile("cp.async.wait_group 2;");
        else if (t + 2 <= T) asm volatile("cp.async.wait_group 1;");
        else asm volatile("cp.async.wait_group 0;");
        __syncthreads();
        if (t + 3 < T) {
            int sl = (t + 3) & 3;
            #pragma unroll
            for (int cch = 0; cch < ACH; cch++) {
                int ch = tid + cch * 256;
                int row_ = ch >> 2, off = (ch & 3) * 8;
                cpa16(As_u + (sl * ASLOT + row_ * SH + off) * 2,
                      A + (size_t)(m0 + row_) * K + (t + 3) * 32 + off);
            }
            #pragma unroll
            for (int cch = 0; cch < 2; cch++) {
                int ch = tid + cch * 256;
                int row_ = ch >> 2, off = (ch & 3) * 8;
                cpa16(Bs_u + (sl * BSLOT + row_ * SH + off) * 2,
                      W + (size_t)(n0 + row_) * K + (t + 3) * 32 + off);
            }
            asm volatile("cp.async.commit_group;");
        }
        const __half* Ast = As + (t & 3) * ASLOT;
        const __half* Bst = Bs + (t & 3) * BSLOT;

        // --- load ALL fragments for both kk halves first ---
        uint2 afA0[MI], afB0[MI], afA1[MI], afB1[MI];
        uint2 bf0[4], bf1[4];
        #pragma unroll
        for (int mi = 0; mi < MI; mi++) {
            int mr = wm * (MT / 2) + mi * 16 + lr4;
            afA0[mi] = *(const uint2*)&Ast[mr * SH + 4 * j];
            afB0[mi] = *(const uint2*)&Ast[(mr + 8) * SH + 4 * j];
            afA1[mi] = *(const uint2*)&Ast[mr * SH + 16 + 4 * j];
            afB1[mi] = *(const uint2*)&Ast[(mr + 8) * SH + 16 + 4 * j];
        }
        #pragma unroll
        for (int ni = 0; ni < 4; ni++) {
            int nr = wn * 32 + ni * 8 + lr4;
            bf0[ni] = *(const uint2*)&Bst[nr * SH + 4 * j];
            bf1[ni] = *(const uint2*)&Bst[nr * SH + 16 + 4 * j];
        }
        // --- 32 MMAs ---
        #pragma unroll
        for (int ni = 0; ni < 4; ni++)
            #pragma unroll
            for (int mi = 0; mi < MI; mi++)
                mma_f16(acc[mi][ni], afA0[mi].x, afB0[mi].x,
                        afA0[mi].y, afB0[mi].y, bf0[ni].x, bf0[ni].y);
        #pragma unroll
        for (int ni = 0; ni < 4; ni++)
            #pragma unroll
            for (int mi = 0; mi < MI; mi++)
                mma_f16(acc[mi][ni], afA1[mi].x, afB1[mi].x,
                        afA1[mi].y, afB1[mi].y, bf1[ni].x, bf1[ni].y);
    }

    #pragma unroll
    for (int mi = 0; mi < MI; mi++) {
        int r = m0 + wm * (MT / 2) + mi * 16 + lr4;
        #pragma unroll
        for (int ni = 0; ni < 4; ni++) {
            int c = n0 + wn * 32 + ni * 8 + 2 * j;
            float v[4] = {acc[mi][ni][0], acc[mi][ni][1], acc[mi][ni][2], acc[mi][ni][3]};
            int rr[2] = {r, r + 8};
            #pragma unroll
            for (int half_ = 0; half_ < 2; half_++) {
                float x0 = v[half_ * 2 + 0], x1 = v[half_ * 2 + 1];
                if (EPI == 0) {
                    if (c < 768) {
                        int dst = pairdst(c);
                        *(__half2*)(Ch + (size_t)rr[half_] * N + dst) =
                            __floats2half2_rn(x0, x1);
                    } else {
                        int b_ = rr[half_] >> 10;
                        int n_ = rr[half_] & (SEQ - 1);
                        int np = perm16h(n_);
                        int d0 = c - 768;
                        __half* vtb = vt + ((size_t)b_ * NH * HD + d0) * SEQ;
                        vtb[np]       = __float2half_rn(x0);
                        vtb[SEQ + np] = __float2half_rn(x1);
                    }
                }
                if (EPI == 1) {
                    const float* rrow = res + (size_t)rr[half_] * N;
                    x0 += bias[c] + rrow[c];
                    x1 += bias[c + 1] + rrow[c + 1];
                    *(float2*)(Cf + (size_t)rr[half_] * N + c) = make_float2(x0, x1);
                }
                if (EPI == 2) {
                    x0 += bias[c];
                    x1 += bias[c + 1];
                    x0 = 0.5f * x0 * (1.0f + erff(x0 * 0.70710678118654752f));
                    x1 = 0.5f * x1 * (1.0f + erff(x1 * 0.70710678118654752f));
                    int dst = pairdst(c);
                    *(__half2*)(Ch + (size_t)rr[half_] * N + dst) =
                        __floats2half2_rn(x0, x1);
                }
            }
        }
    }
}

// ============================================================
// L2Q attention, fp16 mma (R9, unchanged): 256 thr / 8 warps,
// Q tile 128, K tile 64, double-buffered cp.async, warp-private F.
// ============================================================
#define AKH 80
#define KV_TILE (64*AKH)
#define FPAD (16*AKH)
#define ATTN_SMEM ((4*KV_TILE + 8*FPAD) * 2)   // 61440 B

__global__ __launch_bounds__(256, 3)
void attn_tc(const __half* __restrict__ qkv, const __half* __restrict__ vt,
             const float* __restrict__ alpha, const float* __restrict__ beta,
             const float* __restrict__ gamma, __half* __restrict__ ao) {
    extern __shared__ __half smh[];
    __half* Ks = smh;
    __half* Vs = smh + 2 * KV_TILE;
    __half* Fw = smh + 4 * KV_TILE;
    uint32_t Ks_u = (uint32_t)__cvta_generic_to_shared(Ks);
    uint32_t Vs_u = (uint32_t)__cvta_generic_to_shared(Vs);

    int tid = threadIdx.x, lane = tid & 31, wid = tid >> 5;
    int j = lane & 3, lr4 = lane >> 2;
    int bh = blockIdx.y;
    int b = bh / NH, h = bh % NH;
    int r0 = blockIdx.x * 128;
    float al = alpha[h], be = beta[h], ga = gamma[h];

    const __half* qbase = qkv + (size_t)b * SEQ * (3 * DIMC) + h * HD;
    const __half* kbase = qbase + DIMC;
    const __half* vtb = vt + (size_t)bh * HD * SEQ;

    int row0 = wid * 16 + lr4;
    __half* fw = Fw + wid * FPAD;

    uint32_t qf[4][4];
    {
        const __half* qlo = qbase + (size_t)(r0 + row0) * (3 * DIMC);
        const __half* qhi = qlo + 8 * (3 * DIMC);
        #pragma unroll
        for (int dk = 0; dk < 4; dk++) {
            uint2 q0 = *(const uint2*)(qlo + dk * 16 + 4 * j);
            uint2 q1 = *(const uint2*)(qhi + dk * 16 + 4 * j);
            qf[dk][0] = q0.x; qf[dk][1] = q1.x;
            qf[dk][2] = q0.y; qf[dk][3] = q1.y;
        }
    }

    float oacc[8][4];
    #pragma unroll
    for (int i = 0; i < 8; i++)
        #pragma unroll
        for (int r = 0; r < 4; r++) oacc[i][r] = 0.f;
    float den0 = 0.f, den1 = 0.f;

    int lrow = tid >> 2;
    int lq = (tid & 3) * 16;
    uint32_t s_off = (lrow * AKH + lq) * 2;

    {
        const __half* kr = kbase + (size_t)lrow * (3 * DIMC) + lq;
        const __half* vr = vtb + (size_t)lrow * SEQ + lq;
        cpa16(Ks_u + s_off,      kr);
        cpa16(Ks_u + s_off + 16, kr + 8);
        cpa16(Vs_u + s_off,      vr);
        cpa16(Vs_u + s_off + 16, vr + 8);
        asm volatile("cp.async.commit_group;");
    }

    const int NT = SEQ / 64;
    for (int t = 0; t < NT; t++) {
        int s = t & 1;
        asm volatile("cp.async.wait_group 0;");
        __syncthreads();
        if (t + 1 < NT) {
            int s2 = s ^ 1;
            const __half* kr = kbase + (size_t)((t + 1) * 64 + lrow) * (3 * DIMC) + lq;
            const __half* vr = vtb + (size_t)lrow * SEQ + (t + 1) * 64 + lq;
            uint32_t kb = Ks_u + s2 * KV_TILE * 2 + s_off;
            uint32_t vb = Vs_u + s2 * KV_TILE * 2 + s_off;
            cpa16(kb, kr);      cpa16(kb + 16, kr + 8);
            cpa16(vb, vr);      cpa16(vb + 16, vr + 8);
            asm volatile("cp.async.commit_group;");
        }
        const __half* Kt = Ks + s * KV_TILE;
        const __half* Vt = Vs + s * KV_TILE;

        #pragma unroll
        for (int ni = 0; ni < 8; ni++) {
            float sa[4] = {0.f, 0.f, 0.f, 0.f};
            int br = ni * 8 + lr4;
            #pragma unroll
            for (int dk = 0; dk < 4; dk++) {
                uint2 bf = *(const uint2*)&Kt[br * AKH + dk * 16 + 4 * j];
                mma_f16(sa, qf[dk][0], qf[dk][1], qf[dk][2], qf[dk][3], bf.x, bf.y);
            }
            float s0 = sa[0] * 0.125f, s1 = sa[1] * 0.125f;
            float s2 = sa[2] * 0.125f, s3 = sa[3] * 0.125f;
            float f0 = fmaxf(fmaf(al * s0, s0, fmaf(be, s0, ga)), 0.f);
            float f1 = fmaxf(fmaf(al * s1, s1, fmaf(be, s1, ga)), 0.f);
            float f2 = fmaxf(fmaf(al * s2, s2, fmaf(be, s2, ga)), 0.f);
            float f3 = fmaxf(fmaf(al * s3, s3, fmaf(be, s3, ga)), 0.f);
            den0 += f0 + f1;
            den1 += f2 + f3;
            int dst = pairdst(ni * 8 + 2 * j);
            *(__half2*)&fw[lr4 * AKH + dst]       = __floats2half2_rn(f0, f1);
            *(__half2*)&fw[(lr4 + 8) * AKH + dst] = __floats2half2_rn(f2, f3);
        }
        __syncwarp();

        #pragma unroll
        for (int kk = 0; kk < 64; kk += 16) {
            uint2 fa0 = *(const uint2*)&fw[lr4 * AKH + kk + 4 * j];
            uint2 fa1 = *(const uint2*)&fw[(lr4 + 8) * AKH + kk + 4 * j];
            #pragma unroll
            for (int ni = 0; ni < 8; ni++) {
                int nd = ni * 8 + lr4;
                uint2 bf = *(const uint2*)&Vt[nd * AKH + kk + 4 * j];
                mma_f16(oacc[ni], fa0.x, fa1.x, fa0.y, fa1.y, bf.x, bf.y);
            }
        }
        __syncwarp();
    }

    den0 += __shfl_xor_sync(0xffffffff, den0, 1);
    den0 += __shfl_xor_sync(0xffffffff, den0, 2);
    den1 += __shfl_xor_sync(0xffffffff, den1, 1);
    den1 += __shfl_xor_sync(0xffffffff, den1, 2);
    float di0 = 1.0f / (den0 + 1e-6f);
    float di1 = 1.0f / (den1 + 1e-6f);

    __half* olo = ao + (size_t)(b * SEQ + r0 + row0) * DIMC + h * HD;
    __half* ohi = olo + 8 * DIMC;
    #pragma unroll
    for (int ni = 0; ni < 8; ni++) {
        int dst = pairdst(ni * 8 + 2 * j);
        *(__half2*)(olo + dst) = __floats2half2_rn(oacc[ni][0] * di0, oacc[ni][1] * di0);
        *(__half2*)(ohi + dst) = __floats2half2_rn(oacc[ni][2] * di1, oacc[ni][3] * di1);
    }
}

// ============================================================
// launch
// ============================================================
extern "C" void kernel_launch(void* const* d_in, const int* in_sizes, int n_in,
                              void* d_out, int out_size) {
    const float* x      = (const float*)d_in[0];
    const float* qkv_w  = (const float*)d_in[1];
    const float* proj_w = (const float*)d_in[2];
    const float* proj_b = (const float*)d_in[3];
    const float* alpha  = (const float*)d_in[4];
    const float* beta   = (const float*)d_in[5];
    const float* gamma  = (const float*)d_in[6];
    const float* ln1_w  = (const float*)d_in[7];
    const float* ln1_b  = (const float*)d_in[8];
    const float* ln2_w  = (const float*)d_in[9];
    const float* ln2_b  = (const float*)d_in[10];
    const float* w1     = (const float*)d_in[11];
    const float* b1     = (const float*)d_in[12];
    const float* w2     = (const float*)d_in[13];
    const float* b2     = (const float*)d_in[14];
    float* out = (float*)d_out;

    __half *h, *qkv, *vt, *ao, *m, *wq, *wp, *ww1, *ww2;
    float *x1;
    cudaGetSymbolAddress((void**)&h,   g_h);
    cudaGetSymbolAddress((void**)&qkv, g_qkv);
    cudaGetSymbolAddress((void**)&vt,  g_vt);
    cudaGetSymbolAddress((void**)&ao,  g_ao);
    cudaGetSymbolAddress((void**)&x1,  g_x1);
    cudaGetSymbolAddress((void**)&m,   g_m);
    cudaGetSymbolAddress((void**)&wq,  g_wq);
    cudaGetSymbolAddress((void**)&wp,  g_wp);
    cudaGetSymbolAddress((void**)&ww1, g_w1);
    cudaGetSymbolAddress((void**)&ww2, g_w2);

    cudaFuncSetAttribute((const void*)gemm_tc<0,128>, cudaFuncAttributeMaxDynamicSharedMemorySize, GEMM_SMEM(128));
    cudaFuncSetAttribute((const void*)gemm_tc<2,128>, cudaFuncAttributeMaxDynamicSharedMemorySize, GEMM_SMEM(128));
    cudaFuncSetAttribute((const void*)gemm_tc<1,64>,  cudaFuncAttributeMaxDynamicSharedMemorySize, GEMM_SMEM(64));
    cudaFuncSetAttribute((const void*)attn_tc,        cudaFuncAttributeMaxDynamicSharedMemorySize, ATTN_SMEM);

    round_w<<<(NW_1 / 8 + 255) / 256, 256>>>(qkv_w, wq, proj_w, wp, w1, ww1, w2, ww2);
    ln_kernel<<<M_TOT / 8, 256>>>(x, ln1_w, ln1_b, h);
    gemm_tc<0,128><<<dim3(3 * DIMC / 128, M_TOT / 128), 256, GEMM_SMEM(128)>>>(
        h, wq, nullptr, nullptr, nullptr, qkv, vt, M_TOT, 3 * DIMC, DIMC);
    attn_tc<<<dim3(SEQ / 128, BATCH * NH), 256, ATTN_SMEM>>>(qkv, vt, alpha, beta, gamma, ao);
    gemm_tc<1,64><<<dim3(DIMC / 128, M_TOT / 64), 256, GEMM_SMEM(64)>>>(
        ao, wp, proj_b, x, x1, nullptr, nullptr, M_TOT, DIMC, DIMC);
    ln_kernel<<<M_TOT / 8, 256>>>(x1, ln2_w, ln2_b, h);
    gemm_tc<2,128><<<dim3(MLPD / 128, M_TOT / 128), 256, GEMM_SMEM(128)>>>(
        h, ww1, b1, nullptr, nullptr, m, nullptr, M_TOT, MLPD, DIMC);
    gemm_tc<1,64><<<dim3(DIMC / 128, M_TOT / 64), 256, GEMM_SMEM(64)>>>(
        m, ww2, b2, x1, out, nullptr, nullptr, M_TOT, DIMC, MLPD);
}

// round 12
// speedup vs baseline: 1.0923x; 1.0297x over previous
#include <cuda_runtime.h>
#include <cuda_fp16.h>
#include <math.h>
#include <stdint.h>

#define DIMC 384
#define NH 6
#define HD 64
#define MLPD 1536
#define BATCH 8
#define SEQ 1024
#define M_TOT (BATCH*SEQ)
#define LN_EPS 1e-5f

#define NW_QKV (3*DIMC*DIMC)
#define NW_PROJ (DIMC*DIMC)
#define NW_1 (MLPD*DIMC)
#define NW_2 (DIMC*MLPD)

__device__ __half g_h[M_TOT * DIMC];
__device__ __half g_qkv[M_TOT * 3 * DIMC];
__device__ __half g_vt[BATCH * NH * HD * SEQ];
__device__ __half g_ao[M_TOT * DIMC];
__device__ float  g_x1[M_TOT * DIMC];
__device__ __half g_m[M_TOT * MLPD];
__device__ __half g_wq[NW_QKV];
__device__ __half g_wp[NW_PROJ];
__device__ __half g_w1[NW_1];
__device__ __half g_w2[NW_2];

// fp16 pair permutation within 16-element k-groups: pair p -> slot (p%4)*2 + p/4,
// so an 8-byte load at half-offset 4j yields pairs (j, j+4) = one m16n8k16
// fragment register pair.
__device__ __forceinline__ int perm16h(int c) {
    int p = (c >> 1) & 7;
    int s = ((p & 3) << 1) | (p >> 2);
    return (c & ~15) | (s << 1) | (c & 1);
}
__device__ __forceinline__ int pairdst(int c0) {
    int p = (c0 >> 1) & 7;
    int s = ((p & 3) << 1) | (p >> 2);
    return (c0 & ~15) | (s << 1);
}

__device__ __forceinline__ void mma_f16(float c[4], uint32_t a0, uint32_t a1,
                                        uint32_t a2, uint32_t a3,
                                        uint32_t b0, uint32_t b1) {
    asm volatile(
        "mma.sync.aligned.m16n8k16.row.col.f32.f16.f16.f32 "
        "{%0,%1,%2,%3},{%4,%5,%6,%7},{%8,%9},{%0,%1,%2,%3};\n"
        : "+f"(c[0]), "+f"(c[1]), "+f"(c[2]), "+f"(c[3])
        : "r"(a0), "r"(a1), "r"(a2), "r"(a3), "r"(b0), "r"(b1));
}

__device__ __forceinline__ void cpa16(uint32_t s, const void* g) {
    asm volatile("cp.async.cg.shared.global [%0], [%1], 16;" :: "r"(s), "l"(g));
}

// sigmoid-form tanh-GELU: max abs err ~3e-4 (below fp16 storage quantization)
__device__ __forceinline__ float gelu_fast(float x) {
    float w = x * fmaf(-0.0713548162f, x * x, -1.5957691216f);
    return __fdividef(x, 1.0f + __expf(w));
}

// ============================================================
// Fused prep: blocks [0,1024) do LN1; blocks [1024,1312) round
// the four weight matrices to fp16 (pair-permuted along K).
// ============================================================
__global__ __launch_bounds__(256)
void prep_kernel(const float* __restrict__ x, const float* __restrict__ lw,
                 const float* __restrict__ lb, __half* __restrict__ out,
                 const float* __restrict__ a, __half* __restrict__ oa,
                 const float* __restrict__ b, __half* __restrict__ ob,
                 const float* __restrict__ c, __half* __restrict__ oc,
                 const float* __restrict__ d, __half* __restrict__ od) {
    if (blockIdx.x < 1024) {
        int lane = threadIdx.x & 31;
        int row = blockIdx.x * 8 + (threadIdx.x >> 5);
        const float* xr = x + (size_t)row * DIMC;
        float v[12];
        float s = 0.f;
        #pragma unroll
        for (int i = 0; i < 12; i++) { v[i] = xr[lane + 32 * i]; s += v[i]; }
        #pragma unroll
        for (int o = 16; o > 0; o >>= 1) s += __shfl_xor_sync(0xffffffff, s, o);
        float mean = s * (1.0f / DIMC);
        float q = 0.f;
        #pragma unroll
        for (int i = 0; i < 12; i++) { float dd = v[i] - mean; q += dd * dd; }
        #pragma unroll
        for (int o = 16; o > 0; o >>= 1) q += __shfl_xor_sync(0xffffffff, q, o);
        float r = rsqrtf(q * (1.0f / DIMC) + LN_EPS);
        __half* orow = out + (size_t)row * DIMC;
        #pragma unroll
        for (int i = 0; i < 12; i++) {
            int cc = lane + 32 * i;
            orow[perm16h(cc)] = __float2half_rn((v[i] - mean) * r * lw[cc] + lb[cc]);
        }
    } else {
        int i0 = ((blockIdx.x - 1024) * 256 + threadIdx.x) * 8;
        #pragma unroll
        for (int g = 0; g < 2; g++) {
            int i = i0 + g * 4;
            float4 va, vb, vc, vd;
            bool da = i < NW_QKV, db = i < NW_PROJ, dc = i < NW_1;
            if (da) va = *(const float4*)(a + i);
            if (db) vb = *(const float4*)(b + i);
            if (dc) { vc = *(const float4*)(c + i); vd = *(const float4*)(d + i); }
            const float* pa = &va.x; const float* pb = &vb.x;
            const float* pc = &vc.x; const float* pd = &vd.x;
            #pragma unroll
            for (int u = 0; u < 4; u++) {
                int p = perm16h(i + u);
                if (da) oa[p] = __float2half_rn(pa[u]);
                if (db) ob[p] = __float2half_rn(pb[u]);
                if (dc) { oc[p] = __float2half_rn(pc[u]); od[p] = __float2half_rn(pd[u]); }
            }
        }
    }
}

// ============================================================
// LayerNorm (standalone, for LN2)
// ============================================================
__global__ __launch_bounds__(256)
void ln_kernel(const float* __restrict__ x, const float* __restrict__ w,
               const float* __restrict__ b, __half* __restrict__ out) {
    int lane = threadIdx.x & 31;
    int row = blockIdx.x * 8 + (threadIdx.x >> 5);
    const float* xr = x + (size_t)row * DIMC;

    float v[12];
    float s = 0.f;
    #pragma unroll
    for (int i = 0; i < 12; i++) { v[i] = xr[lane + 32 * i]; s += v[i]; }
    #pragma unroll
    for (int o = 16; o > 0; o >>= 1) s += __shfl_xor_sync(0xffffffff, s, o);
    float mean = s * (1.0f / DIMC);

    float q = 0.f;
    #pragma unroll
    for (int i = 0; i < 12; i++) { float d = v[i] - mean; q += d * d; }
    #pragma unroll
    for (int o = 16; o > 0; o >>= 1) q += __shfl_xor_sync(0xffffffff, q, o);
    float r = rsqrtf(q * (1.0f / DIMC) + LN_EPS);

    __half* orow = out + (size_t)row * DIMC;
    #pragma unroll
    for (int i = 0; i < 12; i++) {
        int c = lane + 32 * i;
        orow[perm16h(c)] = __float2half_rn((v[i] - mean) * r * w[c] + b[c]);
    }
}

// ============================================================
// FP16 TC GEMM (R9 structure): BK=32, 4-stage cp.async
// (wait_group 2), 256 thr, warps 2x4, smem stride 48 halfs.
// EPI 0: qkv out (Q/K perm16h; V transposed+permuted to vt)
// EPI 1: +bias +res, fp32 out   EPI 2: +bias, fast GELU, fp16 perm out
// ============================================================
#define SH 48
#define GEMM_SMEM(MT) (4 * ((MT) + 128) * SH * 2)

template <int EPI, int MT>
__global__ __launch_bounds__(256, 2)
void gemm_tc(const __half* __restrict__ A, const __half* __restrict__ W,
             const float* __restrict__ bias, const float* __restrict__ res,
             float* __restrict__ Cf, __half* __restrict__ Ch,
             __half* __restrict__ vt, int M, int N, int K) {
    extern __shared__ __half smemh[];
    const int ASLOT = MT * SH;
    const int BSLOT = 128 * SH;
    __half* As = smemh;                  // [4][ASLOT]
    __half* Bs = smemh + 4 * ASLOT;      // [4][BSLOT]
    uint32_t As_u = (uint32_t)__cvta_generic_to_shared(As);
    uint32_t Bs_u = (uint32_t)__cvta_generic_to_shared(Bs);

    int tid = threadIdx.x;
    int lane = tid & 31, wid = tid >> 5;
    int wm = wid >> 2, wn = wid & 3;
    int j = lane & 3, lr4 = lane >> 2;
    int m0 = blockIdx.y * MT, n0 = blockIdx.x * 128;

    const int ACH = MT / 64;             // A 16B-chunks per thread (2 or 1)
    const int MI = MT / 32;
    float acc[MI][4][4];
    #pragma unroll
    for (int mi = 0; mi < MI; mi++)
        #pragma unroll
        for (int ni = 0; ni < 4; ni++)
            #pragma unroll
            for (int r = 0; r < 4; r++) acc[mi][ni][r] = 0.f;

    int T = K / 32;

    // prologue: stages 0..2
    #pragma unroll
    for (int t = 0; t < 3; t++) {
        #pragma unroll
        for (int cch = 0; cch < ACH; cch++) {
            int ch = tid + cch * 256;
            int row_ = ch >> 2, off = (ch & 3) * 8;
            cpa16(As_u + (t * ASLOT + row_ * SH + off) * 2,
                  A + (size_t)(m0 + row_) * K + t * 32 + off);
        }
        #pragma unroll
        for (int cch = 0; cch < 2; cch++) {
            int ch = tid + cch * 256;
            int row_ = ch >> 2, off = (ch & 3) * 8;
            cpa16(Bs_u + (t * BSLOT + row_ * SH + off) * 2,
                  W + (size_t)(n0 + row_) * K + t * 32 + off);
        }
        asm volatile("cp.async.commit_group;");
    }

    for (int t = 0; t < T; t++) {
        if (t + 3 <= T) asm volatile("cp.async.wait_group 2;");
        else if (t + 2 <= T) asm volatile("cp.async.wait_group 1;");
        else asm volatile("cp.async.wait_group 0;");
        __syncthreads();
        if (t + 3 < T) {
            int sl = (t + 3) & 3;
            #pragma unroll
            for (int cch = 0; cch < ACH; cch++) {
                int ch = tid + cch * 256;
                int row_ = ch >> 2, off = (ch & 3) * 8;
                cpa16(As_u + (sl * ASLOT + row_ * SH + off) * 2,
                      A + (size_t)(m0 + row_) * K + (t + 3) * 32 + off);
            }
            #pragma unroll
            for (int cch = 0; cch < 2; cch++) {
                int ch = tid + cch * 256;
                int row_ = ch >> 2, off = (ch & 3) * 8;
                cpa16(Bs_u + (sl * BSLOT + row_ * SH + off) * 2,
                      W + (size_t)(n0 + row_) * K + (t + 3) * 32 + off);
            }
            asm volatile("cp.async.commit_group;");
        }
        const __half* Ast = As + (t & 3) * ASLOT;
        const __half* Bst = Bs + (t & 3) * BSLOT;
        #pragma unroll
        for (int kk = 0; kk < 32; kk += 16) {
            uint2 afA[MI], afB[MI];
            #pragma unroll
            for (int mi = 0; mi < MI; mi++) {
                int mr = wm * (MT / 2) + mi * 16 + lr4;
                afA[mi] = *(const uint2*)&Ast[mr * SH + kk + 4 * j];
                afB[mi] = *(const uint2*)&Ast[(mr + 8) * SH + kk + 4 * j];
            }
            #pragma unroll
            for (int ni = 0; ni < 4; ni++) {
                int nr = wn * 32 + ni * 8 + lr4;
                uint2 bf = *(const uint2*)&Bst[nr * SH + kk + 4 * j];
                #pragma unroll
                for (int mi = 0; mi < MI; mi++)
                    mma_f16(acc[mi][ni], afA[mi].x, afB[mi].x,
                            afA[mi].y, afB[mi].y, bf.x, bf.y);
            }
        }
    }

    #pragma unroll
    for (int mi = 0; mi < MI; mi++) {
        int r = m0 + wm * (MT / 2) + mi * 16 + lr4;
        #pragma unroll
        for (int ni = 0; ni < 4; ni++) {
            int c = n0 + wn * 32 + ni * 8 + 2 * j;
            float v[4] = {acc[mi][ni][0], acc[mi][ni][1], acc[mi][ni][2], acc[mi][ni][3]};
            int rr[2] = {r, r + 8};
            #pragma unroll
            for (int half_ = 0; half_ < 2; half_++) {
                float x0 = v[half_ * 2 + 0], x1 = v[half_ * 2 + 1];
                if (EPI == 0) {
                    if (c < 768) {
                        int dst = pairdst(c);
                        *(__half2*)(Ch + (size_t)rr[half_] * N + dst) =
                            __floats2half2_rn(x0, x1);
                    } else {
                        int b_ = rr[half_] >> 10;
                        int n_ = rr[half_] & (SEQ - 1);
                        int np = perm16h(n_);
                        int d0 = c - 768;
                        __half* vtb = vt + ((size_t)b_ * NH * HD + d0) * SEQ;
                        vtb[np]       = __float2half_rn(x0);
                        vtb[SEQ + np] = __float2half_rn(x1);
                    }
                }
                if (EPI == 1) {
                    const float* rrow = res + (size_t)rr[half_] * N;
                    x0 += bias[c] + rrow[c];
                    x1 += bias[c + 1] + rrow[c + 1];
                    *(float2*)(Cf + (size_t)rr[half_] * N + c) = make_float2(x0, x1);
                }
                if (EPI == 2) {
                    x0 = gelu_fast(x0 + bias[c]);
                    x1 = gelu_fast(x1 + bias[c + 1]);
                    int dst = pairdst(c);
                    *(__half2*)(Ch + (size_t)rr[half_] * N + dst) =
                        __floats2half2_rn(x0, x1);
                }
            }
        }
    }
}

// ============================================================
// L2Q attention, fp16 mma: 256 thr / 8 warps, Q tile 128,
// K tile 64, double-buffered cp.async, warp-private F pad.
// Scale 0.125 folded into alpha/beta.
// ============================================================
#define AKH 80
#define KV_TILE (64*AKH)
#define FPAD (16*AKH)
#define ATTN_SMEM ((4*KV_TILE + 8*FPAD) * 2)   // 61440 B

__global__ __launch_bounds__(256, 3)
void attn_tc(const __half* __restrict__ qkv, const __half* __restrict__ vt,
             const float* __restrict__ alpha, const float* __restrict__ beta,
             const float* __restrict__ gamma, __half* __restrict__ ao) {
    extern __shared__ __half smh[];
    __half* Ks = smh;
    __half* Vs = smh + 2 * KV_TILE;
    __half* Fw = smh + 4 * KV_TILE;
    uint32_t Ks_u = (uint32_t)__cvta_generic_to_shared(Ks);
    uint32_t Vs_u = (uint32_t)__cvta_generic_to_shared(Vs);

    int tid = threadIdx.x, lane = tid & 31, wid = tid >> 5;
    int j = lane & 3, lr4 = lane >> 2;
    int bh = blockIdx.y;
    int b = bh / NH, h = bh % NH;
    int r0 = blockIdx.x * 128;
    // fold ATT_SCALE: f(s*0.125) with raw s
    float al = alpha[h] * 0.015625f, be = beta[h] * 0.125f, ga = gamma[h];

    const __half* qbase = qkv + (size_t)b * SEQ * (3 * DIMC) + h * HD;
    const __half* kbase = qbase + DIMC;
    const __half* vtb = vt + (size_t)bh * HD * SEQ;

    int row0 = wid * 16 + lr4;
    __half* fw = Fw + wid * FPAD;

    uint32_t qf[4][4];
    {
        const __half* qlo = qbase + (size_t)(r0 + row0) * (3 * DIMC);
        const __half* qhi = qlo + 8 * (3 * DIMC);
        #pragma unroll
        for (int dk = 0; dk < 4; dk++) {
            uint2 q0 = *(const uint2*)(qlo + dk * 16 + 4 * j);
            uint2 q1 = *(const uint2*)(qhi + dk * 16 + 4 * j);
            qf[dk][0] = q0.x; qf[dk][1] = q1.x;
            qf[dk][2] = q0.y; qf[dk][3] = q1.y;
        }
    }

    float oacc[8][4];
    #pragma unroll
    for (int i = 0; i < 8; i++)
        #pragma unroll
        for (int r = 0; r < 4; r++) oacc[i][r] = 0.f;
    float den0 = 0.f, den1 = 0.f;

    int lrow = tid >> 2;
    int lq = (tid & 3) * 16;
    uint32_t s_off = (lrow * AKH + lq) * 2;

    {
        const __half* kr = kbase + (size_t)lrow * (3 * DIMC) + lq;
        const __half* vr = vtb + (size_t)lrow * SEQ + lq;
        cpa16(Ks_u + s_off,      kr);
        cpa16(Ks_u + s_off + 16, kr + 8);
        cpa16(Vs_u + s_off,      vr);
        cpa16(Vs_u + s_off + 16, vr + 8);
        asm volatile("cp.async.commit_group;");
    }

    const int NT = SEQ / 64;
    for (int t = 0; t < NT; t++) {
        int s = t & 1;
        asm volatile("cp.async.wait_group 0;");
        __syncthreads();
        if (t + 1 < NT) {
            int s2 = s ^ 1;
            const __half* kr = kbase + (size_t)((t + 1) * 64 + lrow) * (3 * DIMC) + lq;
            const __half* vr = vtb + (size_t)lrow * SEQ + (t + 1) * 64 + lq;
            uint32_t kb = Ks_u + s2 * KV_TILE * 2 + s_off;
            uint32_t vb = Vs_u + s2 * KV_TILE * 2 + s_off;
            cpa16(kb, kr);      cpa16(kb + 16, kr + 8);
            cpa16(vb, vr);      cpa16(vb + 16, vr + 8);
            asm volatile("cp.async.commit_group;");
        }
        const __half* Kt = Ks + s * KV_TILE;
        const __half* Vt = Vs + s * KV_TILE;

        #pragma unroll
        for (int ni = 0; ni < 8; ni++) {
            float sa[4] = {0.f, 0.f, 0.f, 0.f};
            int br = ni * 8 + lr4;
            #pragma unroll
            for (int dk = 0; dk < 4; dk++) {
                uint2 bf = *(const uint2*)&Kt[br * AKH + dk * 16 + 4 * j];
                mma_f16(sa, qf[dk][0], qf[dk][1], qf[dk][2], qf[dk][3], bf.x, bf.y);
            }
            float f0 = fmaxf(fmaf(al * sa[0], sa[0], fmaf(be, sa[0], ga)), 0.f);
            float f1 = fmaxf(fmaf(al * sa[1], sa[1], fmaf(be, sa[1], ga)), 0.f);
            float f2 = fmaxf(fmaf(al * sa[2], sa[2], fmaf(be, sa[2], ga)), 0.f);
            float f3 = fmaxf(fmaf(al * sa[3], sa[3], fmaf(be, sa[3], ga)), 0.f);
            den0 += f0 + f1;
            den1 += f2 + f3;
            int dst = pairdst(ni * 8 + 2 * j);
            *(__half2*)&fw[lr4 * AKH + dst]       = __floats2half2_rn(f0, f1);
            *(__half2*)&fw[(lr4 + 8) * AKH + dst] = __floats2half2_rn(f2, f3);
        }
        __syncwarp();

        #pragma unroll
        for (int kk = 0; kk < 64; kk += 16) {
            uint2 fa0 = *(const uint2*)&fw[lr4 * AKH + kk + 4 * j];
            uint2 fa1 = *(const uint2*)&fw[(lr4 + 8) * AKH + kk + 4 * j];
            #pragma unroll
            for (int ni = 0; ni < 8; ni++) {
                int nd = ni * 8 + lr4;
                uint2 bf = *(const uint2*)&Vt[nd * AKH + kk + 4 * j];
                mma_f16(oacc[ni], fa0.x, fa1.x, fa0.y, fa1.y, bf.x, bf.y);
            }
        }
        __syncwarp();
    }

    den0 += __shfl_xor_sync(0xffffffff, den0, 1);
    den0 += __shfl_xor_sync(0xffffffff, den0, 2);
    den1 += __shfl_xor_sync(0xffffffff, den1, 1);
    den1 += __shfl_xor_sync(0xffffffff, den1, 2);
    float di0 = 1.0f / (den0 + 1e-6f);
    float di1 = 1.0f / (den1 + 1e-6f);

    __half* olo = ao + (size_t)(b * SEQ + r0 + row0) * DIMC + h * HD;
    __half* ohi = olo + 8 * DIMC;
    #pragma unroll
    for (int ni = 0; ni < 8; ni++) {
        int dst = pairdst(ni * 8 + 2 * j);
        *(__half2*)(olo + dst) = __floats2half2_rn(oacc[ni][0] * di0, oacc[ni][1] * di0);
        *(__half2*)(ohi + dst) = __floats2half2_rn(oacc[ni][2] * di1, oacc[ni][3] * di1);
    }
}

// ============================================================
// launch
// ============================================================
extern "C" void kernel_launch(void* const* d_in, const int* in_sizes, int n_in,
                              void* d_out, int out_size) {
    const float* x      = (const float*)d_in[0];
    const float* qkv_w  = (const float*)d_in[1];
    const float* proj_w = (const float*)d_in[2];
    const float* proj_b = (const float*)d_in[3];
    const float* alpha  = (const float*)d_in[4];
    const float* beta   = (const float*)d_in[5];
    const float* gamma  = (const float*)d_in[6];
    const float* ln1_w  = (const float*)d_in[7];
    const float* ln1_b  = (const float*)d_in[8];
    const float* ln2_w  = (const float*)d_in[9];
    const float* ln2_b  = (const float*)d_in[10];
    const float* w1     = (const float*)d_in[11];
    const float* b1     = (const float*)d_in[12];
    const float* w2     = (const float*)d_in[13];
    const float* b2     = (const float*)d_in[14];
    float* out = (float*)d_out;

    __half *h, *qkv, *vt, *ao, *m, *wq, *wp, *ww1, *ww2;
    float *x1;
    cudaGetSymbolAddress((void**)&h,   g_h);
    cudaGetSymbolAddress((void**)&qkv, g_qkv);
    cudaGetSymbolAddress((void**)&vt,  g_vt);
    cudaGetSymbolAddress((void**)&ao,  g_ao);
    cudaGetSymbolAddress((void**)&x1,  g_x1);
    cudaGetSymbolAddress((void**)&m,   g_m);
    cudaGetSymbolAddress((void**)&wq,  g_wq);
    cudaGetSymbolAddress((void**)&wp,  g_wp);
    cudaGetSymbolAddress((void**)&ww1, g_w1);
    cudaGetSymbolAddress((void**)&ww2, g_w2);

    cudaFuncSetAttribute((const void*)gemm_tc<0,128>, cudaFuncAttributeMaxDynamicSharedMemorySize, GEMM_SMEM(128));
    cudaFuncSetAttribute((const void*)gemm_tc<2,128>, cudaFuncAttributeMaxDynamicSharedMemorySize, GEMM_SMEM(128));
    cudaFuncSetAttribute((const void*)gemm_tc<1,64>,  cudaFuncAttributeMaxDynamicSharedMemorySize, GEMM_SMEM(64));
    cudaFuncSetAttribute((const void*)attn_tc,        cudaFuncAttributeMaxDynamicSharedMemorySize, ATTN_SMEM);

    // fused LN1 + weight rounding (independent jobs, one launch)
    int round_blocks = (NW_1 / 8 + 255) / 256;   // 288
    prep_kernel<<<1024 + round_blocks, 256>>>(x, ln1_w, ln1_b, h,
                                              qkv_w, wq, proj_w, wp,
                                              w1, ww1, w2, ww2);
    gemm_tc<0,128><<<dim3(3 * DIMC / 128, M_TOT / 128), 256, GEMM_SMEM(128)>>>(
        h, wq, nullptr, nullptr, nullptr, qkv, vt, M_TOT, 3 * DIMC, DIMC);
    attn_tc<<<dim3(SEQ / 128, BATCH * NH), 256, ATTN_SMEM>>>(qkv, vt, alpha, beta, gamma, ao);
    gemm_tc<1,64><<<dim3(DIMC / 128, M_TOT / 64), 256, GEMM_SMEM(64)>>>(
        ao, wp, proj_b, x, x1, nullptr, nullptr, M_TOT, DIMC, DIMC);
    ln_kernel<<<M_TOT / 8, 256>>>(x1, ln2_w, ln2_b, h);
    gemm_tc<2,128><<<dim3(MLPD / 128, M_TOT / 128), 256, GEMM_SMEM(128)>>>(
        h, ww1, b1, nullptr, nullptr, m, nullptr, M_TOT, MLPD, DIMC);
    gemm_tc<1,64><<<dim3(DIMC / 128, M_TOT / 64), 256, GEMM_SMEM(64)>>>(
        m, ww2, b2, x1, out, nullptr, nullptr, M_TOT, DIMC, MLPD);
}

// round 13
// speedup vs baseline: 1.1326x; 1.0369x over previous
#include <cuda_runtime.h>
#include <cuda_fp16.h>
#include <math.h>
#include <stdint.h>

#define DIMC 384
#define NH 6
#define HD 64
#define MLPD 1536
#define BATCH 8
#define SEQ 1024
#define M_TOT (BATCH*SEQ)
#define LN_EPS 1e-5f

#define NW_QKV (3*DIMC*DIMC)
#define NW_PROJ (DIMC*DIMC)
#define NW_1 (MLPD*DIMC)
#define NW_2 (DIMC*MLPD)

__device__ __half g_h[M_TOT * DIMC];
__device__ __half g_qkv[M_TOT * 3 * DIMC];
__device__ __half g_vt[BATCH * NH * HD * SEQ];
__device__ __half g_ao[M_TOT * DIMC];
__device__ float  g_x1[M_TOT * DIMC];
__device__ __half g_m[M_TOT * MLPD];
__device__ __half g_wq[NW_QKV];
__device__ __half g_wp[NW_PROJ];
__device__ __half g_w1[NW_1];
__device__ __half g_w2[NW_2];

// fp16 pair permutation within 16-element k-groups
__device__ __forceinline__ int perm16h(int c) {
    int p = (c >> 1) & 7;
    int s = ((p & 3) << 1) | (p >> 2);
    return (c & ~15) | (s << 1) | (c & 1);
}
__device__ __forceinline__ int pairdst(int c0) {
    int p = (c0 >> 1) & 7;
    int s = ((p & 3) << 1) | (p >> 2);
    return (c0 & ~15) | (s << 1);
}

__device__ __forceinline__ void mma_f16(float c[4], uint32_t a0, uint32_t a1,
                                        uint32_t a2, uint32_t a3,
                                        uint32_t b0, uint32_t b1) {
    asm volatile(
        "mma.sync.aligned.m16n8k16.row.col.f32.f16.f16.f32 "
        "{%0,%1,%2,%3},{%4,%5,%6,%7},{%8,%9},{%0,%1,%2,%3};\n"
        : "+f"(c[0]), "+f"(c[1]), "+f"(c[2]), "+f"(c[3])
        : "r"(a0), "r"(a1), "r"(a2), "r"(a3), "r"(b0), "r"(b1));
}

__device__ __forceinline__ void cpa16(uint32_t s, const void* g) {
    asm volatile("cp.async.cg.shared.global [%0], [%1], 16;" :: "r"(s), "l"(g));
}

__device__ __forceinline__ uint32_t f22u(float lo, float hi) {
    __half2 h = __floats2half2_rn(lo, hi);
    return *(uint32_t*)&h;
}

// sigmoid-form tanh-GELU: max abs err ~3e-4
__device__ __forceinline__ float gelu_fast(float x) {
    float w = x * fmaf(-0.0713548162f, x * x, -1.5957691216f);
    return __fdividef(x, 1.0f + __expf(w));
}

// ============================================================
// Fused prep: blocks [0,1024) LN1; blocks >=1024 round weights.
// ============================================================
__global__ __launch_bounds__(256)
void prep_kernel(const float* __restrict__ x, const float* __restrict__ lw,
                 const float* __restrict__ lb, __half* __restrict__ out,
                 const float* __restrict__ a, __half* __restrict__ oa,
                 const float* __restrict__ b, __half* __restrict__ ob,
                 const float* __restrict__ c, __half* __restrict__ oc,
                 const float* __restrict__ d, __half* __restrict__ od) {
    if (blockIdx.x < 1024) {
        int lane = threadIdx.x & 31;
        int row = blockIdx.x * 8 + (threadIdx.x >> 5);
        const float* xr = x + (size_t)row * DIMC;
        float v[12];
        float s = 0.f;
        #pragma unroll
        for (int i = 0; i < 12; i++) { v[i] = xr[lane + 32 * i]; s += v[i]; }
        #pragma unroll
        for (int o = 16; o > 0; o >>= 1) s += __shfl_xor_sync(0xffffffff, s, o);
        float mean = s * (1.0f / DIMC);
        float q = 0.f;
        #pragma unroll
        for (int i = 0; i < 12; i++) { float dd = v[i] - mean; q += dd * dd; }
        #pragma unroll
        for (int o = 16; o > 0; o >>= 1) q += __shfl_xor_sync(0xffffffff, q, o);
        float r = rsqrtf(q * (1.0f / DIMC) + LN_EPS);
        __half* orow = out + (size_t)row * DIMC;
        #pragma unroll
        for (int i = 0; i < 12; i++) {
            int cc = lane + 32 * i;
            orow[perm16h(cc)] = __float2half_rn((v[i] - mean) * r * lw[cc] + lb[cc]);
        }
    } else {
        int i0 = ((blockIdx.x - 1024) * 256 + threadIdx.x) * 8;
        #pragma unroll
        for (int g = 0; g < 2; g++) {
            int i = i0 + g * 4;
            float4 va, vb, vc, vd;
            bool da = i < NW_QKV, db = i < NW_PROJ, dc = i < NW_1;
            if (da) va = *(const float4*)(a + i);
            if (db) vb = *(const float4*)(b + i);
            if (dc) { vc = *(const float4*)(c + i); vd = *(const float4*)(d + i); }
            const float* pa = &va.x; const float* pb = &vb.x;
            const float* pc = &vc.x; const float* pd = &vd.x;
            #pragma unroll
            for (int u = 0; u < 4; u++) {
                int p = perm16h(i + u);
                if (da) oa[p] = __float2half_rn(pa[u]);
                if (db) ob[p] = __float2half_rn(pb[u]);
                if (dc) { oc[p] = __float2half_rn(pc[u]); od[p] = __float2half_rn(pd[u]); }
            }
        }
    }
}

// ============================================================
// LayerNorm (standalone, LN2)
// ============================================================
__global__ __launch_bounds__(256)
void ln_kernel(const float* __restrict__ x, const float* __restrict__ w,
               const float* __restrict__ b, __half* __restrict__ out) {
    int lane = threadIdx.x & 31;
    int row = blockIdx.x * 8 + (threadIdx.x >> 5);
    const float* xr = x + (size_t)row * DIMC;

    float v[12];
    float s = 0.f;
    #pragma unroll
    for (int i = 0; i < 12; i++) { v[i] = xr[lane + 32 * i]; s += v[i]; }
    #pragma unroll
    for (int o = 16; o > 0; o >>= 1) s += __shfl_xor_sync(0xffffffff, s, o);
    float mean = s * (1.0f / DIMC);

    float q = 0.f;
    #pragma unroll
    for (int i = 0; i < 12; i++) { float d = v[i] - mean; q += d * d; }
    #pragma unroll
    for (int o = 16; o > 0; o >>= 1) q += __shfl_xor_sync(0xffffffff, q, o);
    float r = rsqrtf(q * (1.0f / DIMC) + LN_EPS);

    __half* orow = out + (size_t)row * DIMC;
    #pragma unroll
    for (int i = 0; i < 12; i++) {
        int c = lane + 32 * i;
        orow[perm16h(c)] = __float2half_rn((v[i] - mean) * r * w[c] + b[c]);
    }
}

// ============================================================
// FP16 TC GEMM: C[M,N] = A[M,K] @ W[N,K]^T (+epilogue)
// BK=32, 4-stage cp.async (wait_group 2), 256 thr, warps 2x4.
// Templated MT x NT tile. Warp tile (MT/2) x (NT/4).
// EPI 0: qkv out   EPI 1: +bias+res fp32 out   EPI 2: GELU fp16 out
// ============================================================
#define SH 48
#define GEMM_SMEM_B 98304     // 4 stages x (MT+NT)=256 rows x 48 halfs x 2B

template <int EPI, int MT, int NT>
__global__ __launch_bounds__(256, 2)
void gemm_tc(const __half* __restrict__ A, const __half* __restrict__ W,
             const float* __restrict__ bias, const float* __restrict__ res,
             float* __restrict__ Cf, __half* __restrict__ Ch,
             __half* __restrict__ vt, int M, int N, int K) {
    extern __shared__ __half smemh[];
    const int ASLOT = MT * SH;
    const int BSLOT = NT * SH;
    __half* As = smemh;                  // [4][ASLOT]
    __half* Bs = smemh + 4 * ASLOT;      // [4][BSLOT]
    uint32_t As_u = (uint32_t)__cvta_generic_to_shared(As);
    uint32_t Bs_u = (uint32_t)__cvta_generic_to_shared(Bs);

    int tid = threadIdx.x;
    int lane = tid & 31, wid = tid >> 5;
    int wm = wid >> 2, wn = wid & 3;
    int j = lane & 3, lr4 = lane >> 2;
    int m0 = blockIdx.y * MT, n0 = blockIdx.x * NT;

    const int ACH = MT / 64;             // A 16B-chunks per thread (2 or 1)
    const int BCH = NT / 64;             // B chunks per thread (2 or 3)
    const int MI = MT / 32;
    const int NI = NT / 32;
    float acc[MI][NI][4];
    #pragma unroll
    for (int mi = 0; mi < MI; mi++)
        #pragma unroll
        for (int ni = 0; ni < NI; ni++)
            #pragma unroll
            for (int r = 0; r < 4; r++) acc[mi][ni][r] = 0.f;

    int T = K / 32;

    #pragma unroll
    for (int t = 0; t < 3; t++) {
        #pragma unroll
        for (int cch = 0; cch < ACH; cch++) {
            int ch = tid + cch * 256;
            int row_ = ch >> 2, off = (ch & 3) * 8;
            cpa16(As_u + (t * ASLOT + row_ * SH + off) * 2,
                  A + (size_t)(m0 + row_) * K + t * 32 + off);
        }
        #pragma unroll
        for (int cch = 0; cch < BCH; cch++) {
            int ch = tid + cch * 256;
            int row_ = ch >> 2, off = (ch & 3) * 8;
            cpa16(Bs_u + (t * BSLOT + row_ * SH + off) * 2,
                  W + (size_t)(n0 + row_) * K + t * 32 + off);
        }
        asm volatile("cp.async.commit_group;");
    }

    for (int t = 0; t < T; t++) {
        if (t + 3 <= T) asm volatile("cp.async.wait_group 2;");
        else if (t + 2 <= T) asm volatile("cp.async.wait_group 1;");
        else asm volatile("cp.async.wait_group 0;");
        __syncthreads();
        if (t + 3 < T) {
            int sl = (t + 3) & 3;
            #pragma unroll
            for (int cch = 0; cch < ACH; cch++) {
                int ch = tid + cch * 256;
                int row_ = ch >> 2, off = (ch & 3) * 8;
                cpa16(As_u + (sl * ASLOT + row_ * SH + off) * 2,
                      A + (size_t)(m0 + row_) * K + (t + 3) * 32 + off);
            }
            #pragma unroll
            for (int cch = 0; cch < BCH; cch++) {
                int ch = tid + cch * 256;
                int row_ = ch >> 2, off = (ch & 3) * 8;
                cpa16(Bs_u + (sl * BSLOT + row_ * SH + off) * 2,
                      W + (size_t)(n0 + row_) * K + (t + 3) * 32 + off);
            }
            asm volatile("cp.async.commit_group;");
        }
        const __half* Ast = As + (t & 3) * ASLOT;
        const __half* Bst = Bs + (t & 3) * BSLOT;
        #pragma unroll
        for (int kk = 0; kk < 32; kk += 16) {
            uint2 afA[MI], afB[MI];
            #pragma unroll
            for (int mi = 0; mi < MI; mi++) {
                int mr = wm * (MT / 2) + mi * 16 + lr4;
                afA[mi] = *(const uint2*)&Ast[mr * SH + kk + 4 * j];
                afB[mi] = *(const uint2*)&Ast[(mr + 8) * SH + kk + 4 * j];
            }
            #pragma unroll
            for (int ni = 0; ni < NI; ni++) {
                int nr = wn * (NT / 4) + ni * 8 + lr4;
                uint2 bf = *(const uint2*)&Bst[nr * SH + kk + 4 * j];
                #pragma unroll
                for (int mi = 0; mi < MI; mi++)
                    mma_f16(acc[mi][ni], afA[mi].x, afB[mi].x,
                            afA[mi].y, afB[mi].y, bf.x, bf.y);
            }
        }
    }

    #pragma unroll
    for (int mi = 0; mi < MI; mi++) {
        int r = m0 + wm * (MT / 2) + mi * 16 + lr4;
        #pragma unroll
        for (int ni = 0; ni < NI; ni++) {
            int c = n0 + wn * (NT / 4) + ni * 8 + 2 * j;
            float v[4] = {acc[mi][ni][0], acc[mi][ni][1], acc[mi][ni][2], acc[mi][ni][3]};
            int rr[2] = {r, r + 8};
            #pragma unroll
            for (int half_ = 0; half_ < 2; half_++) {
                float x0 = v[half_ * 2 + 0], x1 = v[half_ * 2 + 1];
                if (EPI == 0) {
                    if (c < 768) {
                        int dst = pairdst(c);
                        *(__half2*)(Ch + (size_t)rr[half_] * N + dst) =
                            __floats2half2_rn(x0, x1);
                    } else {
                        int b_ = rr[half_] >> 10;
                        int n_ = rr[half_] & (SEQ - 1);
                        int np = perm16h(n_);
                        int d0 = c - 768;
                        __half* vtb = vt + ((size_t)b_ * NH * HD + d0) * SEQ;
                        vtb[np]       = __float2half_rn(x0);
                        vtb[SEQ + np] = __float2half_rn(x1);
                    }
                }
                if (EPI == 1) {
                    const float* rrow = res + (size_t)rr[half_] * N;
                    x0 += bias[c] + rrow[c];
                    x1 += bias[c + 1] + rrow[c + 1];
                    *(float2*)(Cf + (size_t)rr[half_] * N + c) = make_float2(x0, x1);
                }
                if (EPI == 2) {
                    x0 = gelu_fast(x0 + bias[c]);
                    x1 = gelu_fast(x1 + bias[c + 1]);
                    int dst = pairdst(c);
                    *(__half2*)(Ch + (size_t)rr[half_] * N + dst) =
                        __floats2half2_rn(x0, x1);
                }
            }
        }
    }
}

// ============================================================
// L2Q attention: F stays in REGISTERS (S-accum layout == A-frag
// layout for paired 8-key chunks). No F pad, no intra-tile syncs.
// 256 thr / 8 warps, Q tile 128, K tile 64, double-buffered.
// ============================================================
#define AKH 80
#define KV_TILE (64*AKH)
#define ATTN_SMEM (4*KV_TILE*2)   // 40960 B

__global__ __launch_bounds__(256, 3)
void attn_tc(const __half* __restrict__ qkv, const __half* __restrict__ vt,
             const float* __restrict__ alpha, const float* __restrict__ beta,
             const float* __restrict__ gamma, __half* __restrict__ ao) {
    extern __shared__ __half smh[];
    __half* Ks = smh;
    __half* Vs = smh + 2 * KV_TILE;
    uint32_t Ks_u = (uint32_t)__cvta_generic_to_shared(Ks);
    uint32_t Vs_u = (uint32_t)__cvta_generic_to_shared(Vs);

    int tid = threadIdx.x, lane = tid & 31, wid = tid >> 5;
    int j = lane & 3, lr4 = lane >> 2;
    int bh = blockIdx.y;
    int b = bh / NH, h = bh % NH;
    int r0 = blockIdx.x * 128;
    float al = alpha[h] * 0.015625f, be = beta[h] * 0.125f, ga = gamma[h];

    const __half* qbase = qkv + (size_t)b * SEQ * (3 * DIMC) + h * HD;
    const __half* kbase = qbase + DIMC;
    const __half* vtb = vt + (size_t)bh * HD * SEQ;

    int row0 = wid * 16 + lr4;

    uint32_t qf[4][4];
    {
        const __half* qlo = qbase + (size_t)(r0 + row0) * (3 * DIMC);
        const __half* qhi = qlo + 8 * (3 * DIMC);
        #pragma unroll
        for (int dk = 0; dk < 4; dk++) {
            uint2 q0 = *(const uint2*)(qlo + dk * 16 + 4 * j);
            uint2 q1 = *(const uint2*)(qhi + dk * 16 + 4 * j);
            qf[dk][0] = q0.x; qf[dk][1] = q1.x;
            qf[dk][2] = q0.y; qf[dk][3] = q1.y;
        }
    }

    float oacc[8][4];
    #pragma unroll
    for (int i = 0; i < 8; i++)
        #pragma unroll
        for (int r = 0; r < 4; r++) oacc[i][r] = 0.f;
    float den0 = 0.f, den1 = 0.f;

    int lrow = tid >> 2;
    int lq = (tid & 3) * 16;
    uint32_t s_off = (lrow * AKH + lq) * 2;

    {
        const __half* kr = kbase + (size_t)lrow * (3 * DIMC) + lq;
        const __half* vr = vtb + (size_t)lrow * SEQ + lq;
        cpa16(Ks_u + s_off,      kr);
        cpa16(Ks_u + s_off + 16, kr + 8);
        cpa16(Vs_u + s_off,      vr);
        cpa16(Vs_u + s_off + 16, vr + 8);
        asm volatile("cp.async.commit_group;");
    }

    const int NT2 = SEQ / 64;
    for (int t = 0; t < NT2; t++) {
        int s = t & 1;
        asm volatile("cp.async.wait_group 0;");
        __syncthreads();
        if (t + 1 < NT2) {
            int s2 = s ^ 1;
            const __half* kr = kbase + (size_t)((t + 1) * 64 + lrow) * (3 * DIMC) + lq;
            const __half* vr = vtb + (size_t)lrow * SEQ + (t + 1) * 64 + lq;
            uint32_t kb = Ks_u + s2 * KV_TILE * 2 + s_off;
            uint32_t vb = Vs_u + s2 * KV_TILE * 2 + s_off;
            cpa16(kb, kr);      cpa16(kb + 16, kr + 8);
            cpa16(vb, vr);      cpa16(vb + 16, vr + 8);
            asm volatile("cp.async.commit_group;");
        }
        const __half* Kt = Ks + s * KV_TILE;
        const __half* Vt = Vs + s * KV_TILE;

        // per k16 group: two 8-key S chunks -> transform -> O MMAs
        #pragma unroll
        for (int g = 0; g < 4; g++) {
            float saA[4] = {0.f, 0.f, 0.f, 0.f};
            float saB[4] = {0.f, 0.f, 0.f, 0.f};
            int brA = g * 16 + lr4;
            int brB = brA + 8;
            #pragma unroll
            for (int dk = 0; dk < 4; dk++) {
                uint2 bfA = *(const uint2*)&Kt[brA * AKH + dk * 16 + 4 * j];
                uint2 bfB = *(const uint2*)&Kt[brB * AKH + dk * 16 + 4 * j];
                mma_f16(saA, qf[dk][0], qf[dk][1], qf[dk][2], qf[dk][3], bfA.x, bfA.y);
                mma_f16(saB, qf[dk][0], qf[dk][1], qf[dk][2], qf[dk][3], bfB.x, bfB.y);
            }
            float fA0 = fmaxf(fmaf(al * saA[0], saA[0], fmaf(be, saA[0], ga)), 0.f);
            float fA1 = fmaxf(fmaf(al * saA[1], saA[1], fmaf(be, saA[1], ga)), 0.f);
            float fA2 = fmaxf(fmaf(al * saA[2], saA[2], fmaf(be, saA[2], ga)), 0.f);
            float fA3 = fmaxf(fmaf(al * saA[3], saA[3], fmaf(be, saA[3], ga)), 0.f);
            float fB0 = fmaxf(fmaf(al * saB[0], saB[0], fmaf(be, saB[0], ga)), 0.f);
            float fB1 = fmaxf(fmaf(al * saB[1], saB[1], fmaf(be, saB[1], ga)), 0.f);
            float fB2 = fmaxf(fmaf(al * saB[2], saB[2], fmaf(be, saB[2], ga)), 0.f);
            float fB3 = fmaxf(fmaf(al * saB[3], saB[3], fmaf(be, saB[3], ga)), 0.f);
            den0 += fA0 + fA1 + fB0 + fB1;
            den1 += fA2 + fA3 + fB2 + fB3;
            // pack F accumulators directly as A-fragments (no smem!)
            uint32_t a0 = f22u(fA0, fA1);   // row lr4,   keys g16+2j,2j+1
            uint32_t a1 = f22u(fA2, fA3);   // row lr4+8
            uint32_t a2 = f22u(fB0, fB1);   // row lr4,   keys g16+8+2j..
            uint32_t a3 = f22u(fB2, fB3);   // row lr4+8
            #pragma unroll
            for (int ni = 0; ni < 8; ni++) {
                int nd = ni * 8 + lr4;
                uint2 bf = *(const uint2*)&Vt[nd * AKH + g * 16 + 4 * j];
                mma_f16(oacc[ni], a0, a1, a2, a3, bf.x, bf.y);
            }
        }
    }

    den0 += __shfl_xor_sync(0xffffffff, den0, 1);
    den0 += __shfl_xor_sync(0xffffffff, den0, 2);
    den1 += __shfl_xor_sync(0xffffffff, den1, 1);
    den1 += __shfl_xor_sync(0xffffffff, den1, 2);
    float di0 = 1.0f / (den0 + 1e-6f);
    float di1 = 1.0f / (den1 + 1e-6f);

    __half* olo = ao + (size_t)(b * SEQ + r0 + row0) * DIMC + h * HD;
    __half* ohi = olo + 8 * DIMC;
    #pragma unroll
    for (int ni = 0; ni < 8; ni++) {
        int dst = pairdst(ni * 8 + 2 * j);
        *(__half2*)(olo + dst) = __floats2half2_rn(oacc[ni][0] * di0, oacc[ni][1] * di0);
        *(__half2*)(ohi + dst) = __floats2half2_rn(oacc[ni][2] * di1, oacc[ni][3] * di1);
    }
}

// ============================================================
// launch
// ============================================================
extern "C" void kernel_launch(void* const* d_in, const int* in_sizes, int n_in,
                              void* d_out, int out_size) {
    const float* x      = (const float*)d_in[0];
    const float* qkv_w  = (const float*)d_in[1];
    const float* proj_w = (const float*)d_in[2];
    const float* proj_b = (const float*)d_in[3];
    const float* alpha  = (const float*)d_in[4];
    const float* beta   = (const float*)d_in[5];
    const float* gamma  = (const float*)d_in[6];
    const float* ln1_w  = (const float*)d_in[7];
    const float* ln1_b  = (const float*)d_in[8];
    const float* ln2_w  = (const float*)d_in[9];
    const float* ln2_b  = (const float*)d_in[10];
    const float* w1     = (const float*)d_in[11];
    const float* b1     = (const float*)d_in[12];
    const float* w2     = (const float*)d_in[13];
    const float* b2     = (const float*)d_in[14];
    float* out = (float*)d_out;

    __half *h, *qkv, *vt, *ao, *m, *wq, *wp, *ww1, *ww2;
    float *x1;
    cudaGetSymbolAddress((void**)&h,   g_h);
    cudaGetSymbolAddress((void**)&qkv, g_qkv);
    cudaGetSymbolAddress((void**)&vt,  g_vt);
    cudaGetSymbolAddress((void**)&ao,  g_ao);
    cudaGetSymbolAddress((void**)&x1,  g_x1);
    cudaGetSymbolAddress((void**)&m,   g_m);
    cudaGetSymbolAddress((void**)&wq,  g_wq);
    cudaGetSymbolAddress((void**)&wp,  g_wp);
    cudaGetSymbolAddress((void**)&ww1, g_w1);
    cudaGetSymbolAddress((void**)&ww2, g_w2);

    cudaFuncSetAttribute((const void*)gemm_tc<0,128,128>, cudaFuncAttributeMaxDynamicSharedMemorySize, GEMM_SMEM_B);
    cudaFuncSetAttribute((const void*)gemm_tc<2,128,128>, cudaFuncAttributeMaxDynamicSharedMemorySize, GEMM_SMEM_B);
    cudaFuncSetAttribute((const void*)gemm_tc<1,64,192>,  cudaFuncAttributeMaxDynamicSharedMemorySize, GEMM_SMEM_B);
    cudaFuncSetAttribute((const void*)attn_tc,            cudaFuncAttributeMaxDynamicSharedMemorySize, ATTN_SMEM);

    int round_blocks = (NW_1 / 8 + 255) / 256;   // 288
    prep_kernel<<<1024 + round_blocks, 256>>>(x, ln1_w, ln1_b, h,
                                              qkv_w, wq, proj_w, wp,
                                              w1, ww1, w2, ww2);
    gemm_tc<0,128,128><<<dim3(3 * DIMC / 128, M_TOT / 128), 256, GEMM_SMEM_B>>>(
        h, wq, nullptr, nullptr, nullptr, qkv, vt, M_TOT, 3 * DIMC, DIMC);
    attn_tc<<<dim3(SEQ / 128, BATCH * NH), 256, ATTN_SMEM>>>(qkv, vt, alpha, beta, gamma, ao);
    gemm_tc<1,64,192><<<dim3(DIMC / 192, M_TOT / 64), 256, GEMM_SMEM_B>>>(
        ao, wp, proj_b, x, x1, nullptr, nullptr, M_TOT, DIMC, DIMC);
    ln_kernel<<<M_TOT / 8, 256>>>(x1, ln2_w, ln2_b, h);
    gemm_tc<2,128,128><<<dim3(MLPD / 128, M_TOT / 128), 256, GEMM_SMEM_B>>>(
        h, ww1, b1, nullptr, nullptr, m, nullptr, M_TOT, MLPD, DIMC);
    gemm_tc<1,64,192><<<dim3(DIMC / 192, M_TOT / 64), 256, GEMM_SMEM_B>>>(
        m, ww2, b2, x1, out, nullptr, nullptr, M_TOT, DIMC, MLPD);
}